// round 14
// baseline (speedup 1.0000x reference)
#include <cuda_runtime.h>
#include <cuda_fp16.h>
#include <mma.h>
#include <cstdint>

using namespace nvcuda;

#define T_ 16
#define S_ 16
#define W_ 10
#define D_ 512
#define C_ 64
#define K_ 512
#define SW 160        // S_*W_
#define TWOD 1024
#define NP 3072       // 3 * TWOD
#define NIDX (T_ * W_ * 3 * K_)   // 245760 indices
#define M_ (T_ * SW)              // 2560 rows of P

// ---------------------------------------------------------------------------
// Device globals (no allocation allowed)
__device__ __half g_Ah[(size_t)M_ * D_];  // [2560][512] fp16 A
__device__ __half g_Bh[(size_t)NP * D_];  // [3072][512] fp16 B^T
__device__ __half g_Ph[(size_t)M_ * NP];  // P in fp16  [2560][3072]
__device__ float g_r[T_ * W_ * TWOD];     // 160 x 1024  sum_k relu(z)
__device__ float g_g[T_ * W_ * D_];       // 160 x 512
__device__ float g_h3[T_ * W_ * TWOD];    // 160 x 1024 (pre-relu)
__device__ float g_o[T_ * W_ * D_];       // 160 x 512
__device__ unsigned int g_oddor = 0u;     // dtype probe (never reset: atomicOr over
                                          // identical data is idempotent => deterministic)

// ---------------------------------------------------------------------------
__device__ __forceinline__ void cp_async16(void* dst, const void* src) {
    uint32_t d;
    asm("{ .reg .u64 t; cvta.to.shared.u64 t, %1; cvt.u32.u64 %0, t; }" : "=r"(d) : "l"(dst));
    asm volatile("cp.async.cg.shared.global [%0], [%1], 16;" :: "r"(d), "l"(src));
}

// ---------------------------------------------------------------------------
// X (2560x512 fp32) -> fp16 A; zeros g/h3/o; inline dtype probe (odd-word OR:
// int64 layout -> 0, int32 layout -> nonzero w.h.p.).
__global__ void prep_a(const float* __restrict__ x, const unsigned int* __restrict__ raw) {
    int i = blockIdx.x * 256 + threadIdx.x;     // i indexes groups of 4 elements
    unsigned int v = (i < NIDX / 2) ? raw[2 * i + 1] : 0u;
#pragma unroll
    for (int off = 16; off > 0; off >>= 1) v |= __shfl_xor_sync(0xffffffffu, v, off);
    if ((threadIdx.x & 31) == 0 && v) atomicOr(&g_oddor, v);

    if (i < T_ * W_ * TWOD) g_h3[i] = 0.f;
    if (i < T_ * W_ * D_) { g_g[i] = 0.f; g_o[i] = 0.f; }
    if (i >= M_ * D_ / 4) return;
    float4 vv = *(const float4*)(x + (size_t)i * 4);
    __half2 h0 = __floats2half2_rn(vv.x, vv.y);
    __half2 h1 = __floats2half2_rn(vv.z, vv.w);
    uint2 o = {*(uint32_t*)&h0, *(uint32_t*)&h1};
    *(uint2*)(g_Ah + (size_t)i * 4) = o;
}

// W1 (1536 x 1024) -> fp16 B^T [3072][512] via coalesced 32x32 smem transpose.
__global__ __launch_bounds__(256) void prep_b(const float* __restrict__ W1) {
    __shared__ float tile[32][33];
    int o0 = blockIdx.x * 32, k0 = blockIdx.y * 32, s = blockIdx.z;
    int tx = threadIdx.x & 31, ty = threadIdx.x >> 5;   // ty 0..7
#pragma unroll
    for (int i = 0; i < 4; i++) {
        int k = ty + i * 8;
        tile[k][tx] = W1[(size_t)(s * D_ + k0 + k) * TWOD + o0 + tx];
    }
    __syncthreads();
#pragma unroll
    for (int i = 0; i < 4; i++) {
        int o = ty + i * 8;
        g_Bh[(size_t)(s * TWOD + o0 + o) * D_ + k0 + tx] = __float2half_rn(tile[tx][o]);
    }
}

// ---------------------------------------------------------------------------
// fp16 GEMM, fp32 accum: P(fp16 2560x3072) = A (2560x512) @ B^T (3072x512)
// CTA 128x128, 8 warps (warp tile 32x64), BK=32, 4-stage cp.async ring, 2 CTAs/SM.
#define BK 32
#define KPAD 40
#define STG (128 * KPAD)             // halves per matrix per stage (5120)
#define NSTAGE 4
#define NCH (D_ / BK)                // 16 chunks
#define GEMM_SMEM (NSTAGE * 2 * STG * 2)   // 81920 bytes

__global__ __launch_bounds__(256, 2) void gemm_fp16() {
    extern __shared__ __half sh[];   // [4 stages][A 128x40 | B 128x40]

    int tid = threadIdx.x;
    int wid = tid >> 5, lane = tid & 31;
    int warp_m = wid & 3;    // 4 warps along M -> 32 rows each
    int warp_n = wid >> 2;   // 2 warps along N -> 64 cols each
    int row0 = blockIdx.y * 128;
    int col0 = blockIdx.x * 128;

    wmma::fragment<wmma::accumulator, 16, 16, 16, float> acc[2][4];
#pragma unroll
    for (int i = 0; i < 2; i++)
#pragma unroll
        for (int j = 0; j < 4; j++) wmma::fill_fragment(acc[i][j], 0.f);

    auto prefetch = [&](int c) {
        int s = c % NSTAGE;
        __half* As = sh + s * (2 * STG);
        __half* Bs = As + STG;
        int k0 = c * BK;
#pragma unroll
        for (int j = 0; j < 2; j++) {
            int idx = tid + j * 256;
            int r = idx >> 2, q = (idx & 3) * 8;
            cp_async16(&As[r * KPAD + q], g_Ah + (size_t)(row0 + r) * D_ + k0 + q);
            cp_async16(&Bs[r * KPAD + q], g_Bh + (size_t)(col0 + r) * D_ + k0 + q);
        }
        asm volatile("cp.async.commit_group;" ::: "memory");
    };

    prefetch(0);
    prefetch(1);
    prefetch(2);
    for (int c = 0; c < NCH; c++) {
        if (c < NCH - 2) {
            asm volatile("cp.async.wait_group 2;" ::: "memory");
        } else if (c == NCH - 2) {
            asm volatile("cp.async.wait_group 1;" ::: "memory");
        } else {
            asm volatile("cp.async.wait_group 0;" ::: "memory");
        }
        __syncthreads();
        if (c + 3 < NCH) prefetch(c + 3);

        const __half* As = sh + (c % NSTAGE) * (2 * STG);
        const __half* Bs = As + STG;
#pragma unroll
        for (int kk = 0; kk < BK; kk += 16) {
            wmma::fragment<wmma::matrix_a, 16, 16, 16, __half, wmma::row_major> fa[2];
            wmma::fragment<wmma::matrix_b, 16, 16, 16, __half, wmma::col_major> fb[4];
#pragma unroll
            for (int i = 0; i < 2; i++)
                wmma::load_matrix_sync(fa[i], As + (warp_m * 32 + i * 16) * KPAD + kk, KPAD);
#pragma unroll
            for (int j = 0; j < 4; j++)
                wmma::load_matrix_sync(fb[j], Bs + (warp_n * 64 + j * 16) * KPAD + kk, KPAD);
#pragma unroll
            for (int i = 0; i < 2; i++)
#pragma unroll
                for (int j = 0; j < 4; j++)
                    wmma::mma_sync(acc[i][j], fa[i], fb[j], acc[i][j]);
        }
    }
    __syncthreads();

    // Epilogue: per-warp 16x16 float patch in smem, convert to fp16, store P.
    float* patch = (float*)sh + wid * 256;
#pragma unroll
    for (int i = 0; i < 2; i++)
#pragma unroll
        for (int j = 0; j < 4; j++) {
            wmma::store_matrix_sync(patch, acc[i][j], 16, wmma::mem_row_major);
            __syncwarp();
            int m = row0 + warp_m * 32 + i * 16;
            int n = col0 + warp_n * 64 + j * 16;
            int pr = lane >> 1, pc = (lane & 1) * 8;
            __half2 o[4];
#pragma unroll
            for (int e = 0; e < 4; e++)
                o[e] = __floats2half2_rn(patch[pr * 16 + pc + 2 * e],
                                         patch[pr * 16 + pc + 2 * e + 1]);
            *(uint4*)(g_Ph + (size_t)(m + pr) * NP + n + pc) = *(uint4*)o;
            __syncwarp();
        }
}

// ---------------------------------------------------------------------------
// Smem-staged gather, GCW=64, w-split 2: block = (chunk, t, wh) -> 512 blocks.
// Each block handles 5 w-slices. 256 threads = 8 col-slots x 32 k-groups.
// half2 adds, fp32 accum. 3 CTAs/SM by smem -> occ ~36%.
#define GCW 64
#define NKG 32
#define WSPLIT 2
#define WPB (W_ / WSPLIT)                      // 5 w per block
#define PS_HALVES (3 * SW * GCW)               // 30720 halves
#define GSM_BYTES (PS_HALVES * 2 + 3 * K_ * 4 + NKG * GCW * 4)  // 75776

__global__ __launch_bounds__(256) void gather_s(const float* __restrict__ b1,
                                                const int* __restrict__ raw) {
    extern __shared__ char gsm[];
    __half* Ps  = (__half*)gsm;                              // [3][160][64]
    int*   sidx = (int*)(gsm + PS_HALVES * 2);               // [3][512]
    float* part = (float*)(gsm + PS_HALVES * 2 + 3 * K_ * 4); // [32][64]

    int chunk = blockIdx.x;   // 0..15 (64-col chunks of the 1024-wide output)
    int t     = blockIdx.y;   // 0..15
    int w0    = blockIdx.z * WPB;   // 0 or 5
    int tid = threadIdx.x;
    unsigned int is32 = g_oddor;

    // Stage P slice: slot s, row r, cols [s*1024 + chunk*64, +64)
    const __half* Pt = g_Ph + (size_t)t * SW * NP;
    for (int i = tid; i < PS_HALVES / 8; i += 256) {   // 3840 uint4
        int q = i & 7;                 // uint4 within row (8 per 64-half row)
        int r = (i >> 3) % SW;
        int s = i / (8 * SW);
        *(uint4*)(Ps + (s * SW + r) * GCW + q * 8) =
            *(const uint4*)(Pt + (size_t)r * NP + s * 1024 + chunk * GCW + q * 8);
    }

    int cs = (tid & 7) * 8;           // col-slot: 8 halves
    int kg = tid >> 3;                // k-group: 16 k each
    int col = chunk * GCW + cs;
    __half2 bbh[4];
#pragma unroll
    for (int j = 0; j < 4; j++) bbh[j] = __floats2half2_rn(b1[col + 2 * j], b1[col + 2 * j + 1]);
    const __half2 zero2 = __floats2half2_rn(0.f, 0.f);

    for (int wi = 0; wi < WPB; wi++) {
        int w = w0 + wi;
        __syncthreads();   // staging done (wi=0) / part consumers done (wi>0)
        int base = (t * W_ + w) * 3 * K_;
        for (int i = tid; i < 3 * K_; i += 256) {
            int v = is32 ? raw[base + i] : raw[2 * (base + i)];
            sidx[i] = min(max(v, 0), SW - 1);
        }
        __syncthreads();

        float acc[8] = {};
#pragma unroll 4
        for (int k = kg * 16; k < kg * 16 + 16; k++) {
            int a = sidx[k];
            int b = sidx[K_ + k];
            int c = sidx[2 * K_ + k];
            uint4 va = *(uint4*)(Ps + (size_t)a * GCW + cs);
            uint4 vb = *(uint4*)(Ps + (SW + (size_t)b) * GCW + cs);
            uint4 vc = *(uint4*)(Ps + (2 * SW + (size_t)c) * GCW + cs);
            const __half2* ha = (const __half2*)&va;
            const __half2* hb = (const __half2*)&vb;
            const __half2* hc = (const __half2*)&vc;
#pragma unroll
            for (int j = 0; j < 4; j++) {
                __half2 z = __hadd2(__hadd2(ha[j], hb[j]), __hadd2(hc[j], bbh[j]));
                z = __hmax2(z, zero2);
                float2 f = __half22float2(z);
                acc[2 * j]     += f.x;
                acc[2 * j + 1] += f.y;
            }
        }
#pragma unroll
        for (int j = 0; j < 4; j++)
            *(float2*)&part[kg * GCW + cs + 2 * j] = make_float2(acc[2 * j], acc[2 * j + 1]);
        __syncthreads();
        if (tid < GCW) {
            float s = 0.f;
#pragma unroll
            for (int g = 0; g < NKG; g++) s += part[g * GCW + tid];
            g_r[(size_t)(t * W_ + w) * TWOD + chunk * GCW + tid] = s;
        }
    }
}

// ---------------------------------------------------------------------------
// Small-M k-split GEMM: Cm += A[k-slice] @ B[k-slice] (atomicAdd), bias from z==0.
// RELUA applies relu to A elements on load. BM=32, BN=64, BK=16, 256 threads.
template <bool RELUA>
__global__ __launch_bounds__(256) void gemm_ks(const float* __restrict__ A,
                                               const float* __restrict__ B,
                                               const float* __restrict__ bias,
                                               float bscale,
                                               float* __restrict__ Cm,
                                               int M, int N, int Kd) {
    __shared__ float As[16][33];
    __shared__ float Bs[16][64];
    int col0 = blockIdx.x * 64;
    int row0 = blockIdx.y * 32;
    int tid = threadIdx.x;
    int tx = tid & 15, ty = tid >> 4;
    int klen = Kd / gridDim.z;
    int kbeg = blockIdx.z * klen, kend = kbeg + klen;
    float acc[2][4] = {};

    for (int k0 = kbeg; k0 < kend; k0 += 16) {
#pragma unroll
        for (int l = 0; l < 2; l++) {
            int e = tid + l * 256;
            int m = e >> 4, kk = e & 15;
            float v = A[(size_t)(row0 + m) * Kd + k0 + kk];
            if (RELUA) v = fmaxf(v, 0.f);
            As[kk][m] = v;
        }
        {
            int kk = tid >> 4, c = (tid & 15) * 4;
            *(float4*)&Bs[kk][c] = *(const float4*)(B + (size_t)(k0 + kk) * N + col0 + c);
        }
        __syncthreads();
#pragma unroll
        for (int kk = 0; kk < 16; kk++) {
            float a0 = As[kk][ty * 2], a1 = As[kk][ty * 2 + 1];
            float4 b = *(const float4*)&Bs[kk][tx * 4];
            acc[0][0] = fmaf(a0, b.x, acc[0][0]);
            acc[0][1] = fmaf(a0, b.y, acc[0][1]);
            acc[0][2] = fmaf(a0, b.z, acc[0][2]);
            acc[0][3] = fmaf(a0, b.w, acc[0][3]);
            acc[1][0] = fmaf(a1, b.x, acc[1][0]);
            acc[1][1] = fmaf(a1, b.y, acc[1][1]);
            acc[1][2] = fmaf(a1, b.z, acc[1][2]);
            acc[1][3] = fmaf(a1, b.w, acc[1][3]);
        }
        __syncthreads();
    }
#pragma unroll
    for (int i = 0; i < 2; i++) {
        int row = row0 + ty * 2 + i;
#pragma unroll
        for (int j = 0; j < 4; j++) {
            int colx = col0 + tx * 4 + j;
            float v = acc[i][j];
            if (blockIdx.z == 0) v += bias[colx] * bscale;
            atomicAdd(&Cm[(size_t)row * N + colx], v);
        }
    }
}

// ---------------------------------------------------------------------------
// score = o @ Wc + bc, softmax over C_=64. 256 threads: 64 cols x 4 k-slices.
__global__ __launch_bounds__(256) void score_softmax(const float* __restrict__ Wc,
                                                     const float* __restrict__ bc,
                                                     float* __restrict__ out) {
    int row = blockIdx.x;
    int tid = threadIdx.x;
    __shared__ float so[D_];
    __shared__ float part[4][C_];
    __shared__ float red[2], red2[2];
    for (int e = tid; e < D_; e += 256) so[e] = g_o[(size_t)row * D_ + e];
    __syncthreads();

    int col = tid & 63, sl = tid >> 6;
    float acc = (sl == 0) ? bc[col] : 0.f;
#pragma unroll 4
    for (int k = sl * 128; k < sl * 128 + 128; k++)
        acc = fmaf(so[k], Wc[(size_t)k * C_ + col], acc);
    part[sl][col] = acc;
    __syncthreads();

    float sc = 0.f, e = 0.f;
    if (tid < C_) {
        sc = part[0][tid] + part[1][tid] + part[2][tid] + part[3][tid];
        float m = sc;
#pragma unroll
        for (int off = 16; off > 0; off >>= 1) m = fmaxf(m, __shfl_xor_sync(0xffffffffu, m, off));
        if ((tid & 31) == 0) red[tid >> 5] = m;
    }
    __syncthreads();
    if (tid < C_) {
        float m = fmaxf(red[0], red[1]);
        e = expf(sc - m);
        float s = e;
#pragma unroll
        for (int off = 16; off > 0; off >>= 1) s += __shfl_xor_sync(0xffffffffu, s, off);
        if ((tid & 31) == 0) red2[tid >> 5] = s;
    }
    __syncthreads();
    if (tid < C_) out[(size_t)row * C_ + tid] = e / (red2[0] + red2[1]);
}

// ---------------------------------------------------------------------------
extern "C" void kernel_launch(void* const* d_in, const int* in_sizes, int n_in,
                              void* d_out, int out_size) {
    const float* x    = (const float*)d_in[0];
    const void*  tidx = d_in[1];                 // int32 or int64 — probed on device
    const float* W1   = (const float*)d_in[2];
    const float* b1   = (const float*)d_in[3];
    const float* W2   = (const float*)d_in[4];
    const float* b2   = (const float*)d_in[5];
    const float* W3   = (const float*)d_in[6];
    const float* b3   = (const float*)d_in[7];
    const float* W4   = (const float*)d_in[8];
    const float* b4   = (const float*)d_in[9];
    const float* Wc   = (const float*)d_in[10];
    const float* bc   = (const float*)d_in[11];
    float* out = (float*)d_out;

    void *pr, *pg, *ph3, *po;
    cudaGetSymbolAddress(&pr, g_r);
    cudaGetSymbolAddress(&pg, g_g);
    cudaGetSymbolAddress(&ph3, g_h3);
    cudaGetSymbolAddress(&po, g_o);

    cudaFuncSetAttribute(gemm_fp16, cudaFuncAttributeMaxDynamicSharedMemorySize,
                         GEMM_SMEM);
    cudaFuncSetAttribute(gather_s, cudaFuncAttributeMaxDynamicSharedMemorySize,
                         GSM_BYTES);

    // 1) fp16 A + zero accumulators + inline dtype probe
    prep_a<<<(M_ * D_ / 4 + 255) / 256, 256>>>(x, (const unsigned int*)tidx);
    // 2) fp16 B^T (coalesced transpose)
    prep_b<<<dim3(TWOD / 32, D_ / 32, 3), 256>>>(W1);

    // 3) P(fp16) = A @ B^T  (fp16 GEMM, K=512, 4-stage cp.async, 2 CTAs/SM)
    gemm_fp16<<<dim3(NP / 128, M_ / 128), 256, GEMM_SMEM>>>();

    // 4) smem-staged gather+relu+k-sum -> r  (profiled slot; 512 blocks now)
    gather_s<<<dim3(TWOD / GCW, T_, WSPLIT), 256, GSM_BYTES>>>(b1, (const int*)tidx);

    // 5) g = r @ W2 + K_*b2        (160 x 512, K=1024, 16-way k-split)
    gemm_ks<false><<<dim3(D_ / 64, 5, 16), 256>>>(
        (const float*)pr, W2, b2, (float)K_, (float*)pg, T_ * W_, D_, TWOD);

    // 6) h3_pre = g @ W3 + b3      (160 x 1024, K=512, 8-way k-split; relu deferred)
    gemm_ks<false><<<dim3(TWOD / 64, 5, 8), 256>>>(
        (const float*)pg, W3, b3, 1.f, (float*)ph3, T_ * W_, TWOD, D_);

    // 7) o = relu(h3_pre) @ W4 + b4 (160 x 512, K=1024, 16-way k-split)
    gemm_ks<true><<<dim3(D_ / 64, 5, 16), 256>>>(
        (const float*)ph3, W4, b4, 1.f, (float*)po, T_ * W_, D_, TWOD);

    // 8) score + softmax -> out    (160 x 64)
    score_softmax<<<T_ * W_, 256>>>(Wc, bc, out);
}

// round 15
// speedup vs baseline: 1.5343x; 1.5343x over previous
#include <cuda_runtime.h>
#include <cuda_fp16.h>
#include <mma.h>
#include <cstdint>

using namespace nvcuda;

#define T_ 16
#define S_ 16
#define W_ 10
#define D_ 512
#define C_ 64
#define K_ 512
#define SW 160        // S_*W_
#define TWOD 1024
#define NP 3072       // 3 * TWOD
#define NIDX (T_ * W_ * 3 * K_)   // 245760 indices
#define M_ (T_ * SW)              // 2560 rows of P

// ---------------------------------------------------------------------------
// Device globals (no allocation allowed)
__device__ __half g_Ah[(size_t)M_ * D_];  // [2560][512] fp16 A
__device__ __half g_Bh[(size_t)NP * D_];  // [3072][512] fp16 B^T
__device__ __half g_Ph[(size_t)M_ * NP];  // P in fp16  [2560][3072]
__device__ float g_r[T_ * W_ * TWOD];     // 160 x 1024  sum_k relu(z)
__device__ float g_g[T_ * W_ * D_];       // 160 x 512
__device__ float g_h3[T_ * W_ * TWOD];    // 160 x 1024 (pre-relu)
__device__ float g_o[T_ * W_ * D_];       // 160 x 512
__device__ unsigned int g_oddor = 0u;     // dtype probe (never reset: atomicOr over
                                          // identical data is idempotent => deterministic)

// ---------------------------------------------------------------------------
__device__ __forceinline__ void cp_async16(void* dst, const void* src) {
    uint32_t d;
    asm("{ .reg .u64 t; cvta.to.shared.u64 t, %1; cvt.u32.u64 %0, t; }" : "=r"(d) : "l"(dst));
    asm volatile("cp.async.cg.shared.global [%0], [%1], 16;" :: "r"(d), "l"(src));
}

// ---------------------------------------------------------------------------
// X (2560x512 fp32) -> fp16 A; zeros g/h3/o; inline dtype probe (odd-word OR:
// int64 layout -> 0, int32 layout -> nonzero w.h.p.).
__global__ void prep_a(const float* __restrict__ x, const unsigned int* __restrict__ raw) {
    int i = blockIdx.x * 256 + threadIdx.x;     // i indexes groups of 4 elements
    unsigned int v = (i < NIDX / 2) ? raw[2 * i + 1] : 0u;
#pragma unroll
    for (int off = 16; off > 0; off >>= 1) v |= __shfl_xor_sync(0xffffffffu, v, off);
    if ((threadIdx.x & 31) == 0 && v) atomicOr(&g_oddor, v);

    if (i < T_ * W_ * TWOD) g_h3[i] = 0.f;
    if (i < T_ * W_ * D_) { g_g[i] = 0.f; g_o[i] = 0.f; }
    if (i >= M_ * D_ / 4) return;
    float4 vv = *(const float4*)(x + (size_t)i * 4);
    __half2 h0 = __floats2half2_rn(vv.x, vv.y);
    __half2 h1 = __floats2half2_rn(vv.z, vv.w);
    uint2 o = {*(uint32_t*)&h0, *(uint32_t*)&h1};
    *(uint2*)(g_Ah + (size_t)i * 4) = o;
}

// W1 (1536 x 1024) -> fp16 B^T [3072][512] via coalesced 32x32 smem transpose.
__global__ __launch_bounds__(256) void prep_b(const float* __restrict__ W1) {
    __shared__ float tile[32][33];
    int o0 = blockIdx.x * 32, k0 = blockIdx.y * 32, s = blockIdx.z;
    int tx = threadIdx.x & 31, ty = threadIdx.x >> 5;   // ty 0..7
#pragma unroll
    for (int i = 0; i < 4; i++) {
        int k = ty + i * 8;
        tile[k][tx] = W1[(size_t)(s * D_ + k0 + k) * TWOD + o0 + tx];
    }
    __syncthreads();
#pragma unroll
    for (int i = 0; i < 4; i++) {
        int o = ty + i * 8;
        g_Bh[(size_t)(s * TWOD + o0 + o) * D_ + k0 + tx] = __float2half_rn(tile[tx][o]);
    }
}

// ---------------------------------------------------------------------------
// fp16 GEMM, fp32 accum: P(fp16 2560x3072) = A (2560x512) @ B^T (3072x512)
// CTA 128x128, 8 warps (warp tile 32x64), BK=32, 4-stage cp.async ring, 2 CTAs/SM.
#define BK 32
#define KPAD 40
#define STG (128 * KPAD)             // halves per matrix per stage (5120)
#define NSTAGE 4
#define NCH (D_ / BK)                // 16 chunks
#define GEMM_SMEM (NSTAGE * 2 * STG * 2)   // 81920 bytes

__global__ __launch_bounds__(256, 2) void gemm_fp16() {
    extern __shared__ __half sh[];   // [4 stages][A 128x40 | B 128x40]

    int tid = threadIdx.x;
    int wid = tid >> 5, lane = tid & 31;
    int warp_m = wid & 3;    // 4 warps along M -> 32 rows each
    int warp_n = wid >> 2;   // 2 warps along N -> 64 cols each
    int row0 = blockIdx.y * 128;
    int col0 = blockIdx.x * 128;

    wmma::fragment<wmma::accumulator, 16, 16, 16, float> acc[2][4];
#pragma unroll
    for (int i = 0; i < 2; i++)
#pragma unroll
        for (int j = 0; j < 4; j++) wmma::fill_fragment(acc[i][j], 0.f);

    auto prefetch = [&](int c) {
        int s = c % NSTAGE;
        __half* As = sh + s * (2 * STG);
        __half* Bs = As + STG;
        int k0 = c * BK;
#pragma unroll
        for (int j = 0; j < 2; j++) {
            int idx = tid + j * 256;
            int r = idx >> 2, q = (idx & 3) * 8;
            cp_async16(&As[r * KPAD + q], g_Ah + (size_t)(row0 + r) * D_ + k0 + q);
            cp_async16(&Bs[r * KPAD + q], g_Bh + (size_t)(col0 + r) * D_ + k0 + q);
        }
        asm volatile("cp.async.commit_group;" ::: "memory");
    };

    prefetch(0);
    prefetch(1);
    prefetch(2);
    for (int c = 0; c < NCH; c++) {
        if (c < NCH - 2) {
            asm volatile("cp.async.wait_group 2;" ::: "memory");
        } else if (c == NCH - 2) {
            asm volatile("cp.async.wait_group 1;" ::: "memory");
        } else {
            asm volatile("cp.async.wait_group 0;" ::: "memory");
        }
        __syncthreads();
        if (c + 3 < NCH) prefetch(c + 3);

        const __half* As = sh + (c % NSTAGE) * (2 * STG);
        const __half* Bs = As + STG;
#pragma unroll
        for (int kk = 0; kk < BK; kk += 16) {
            wmma::fragment<wmma::matrix_a, 16, 16, 16, __half, wmma::row_major> fa[2];
            wmma::fragment<wmma::matrix_b, 16, 16, 16, __half, wmma::col_major> fb[4];
#pragma unroll
            for (int i = 0; i < 2; i++)
                wmma::load_matrix_sync(fa[i], As + (warp_m * 32 + i * 16) * KPAD + kk, KPAD);
#pragma unroll
            for (int j = 0; j < 4; j++)
                wmma::load_matrix_sync(fb[j], Bs + (warp_n * 64 + j * 16) * KPAD + kk, KPAD);
#pragma unroll
            for (int i = 0; i < 2; i++)
#pragma unroll
                for (int j = 0; j < 4; j++)
                    wmma::mma_sync(acc[i][j], fa[i], fb[j], acc[i][j]);
        }
    }
    __syncthreads();

    // Epilogue: per-warp 16x16 float patch in smem, convert to fp16, store P.
    float* patch = (float*)sh + wid * 256;
#pragma unroll
    for (int i = 0; i < 2; i++)
#pragma unroll
        for (int j = 0; j < 4; j++) {
            wmma::store_matrix_sync(patch, acc[i][j], 16, wmma::mem_row_major);
            __syncwarp();
            int m = row0 + warp_m * 32 + i * 16;
            int n = col0 + warp_n * 64 + j * 16;
            int pr = lane >> 1, pc = (lane & 1) * 8;
            __half2 o[4];
#pragma unroll
            for (int e = 0; e < 4; e++)
                o[e] = __floats2half2_rn(patch[pr * 16 + pc + 2 * e],
                                         patch[pr * 16 + pc + 2 * e + 1]);
            *(uint4*)(g_Ph + (size_t)(m + pr) * NP + n + pc) = *(uint4*)o;
            __syncwarp();
        }
}

// ---------------------------------------------------------------------------
// Smem-staged gather (R13 structure: 256 blocks, no w-split).
// 256 threads = 8 col-slots x 32 k-groups (16 k each).
// fp16 accumulation within each 16-k group (fp32 across groups).
// sidx interleaved [512][4] so one LDS.128 fetches all 3 slot indices.
#define GCW 64
#define NKG 32
#define PS_HALVES (3 * SW * GCW)               // 30720 halves (61440 B)
#define GSM_BYTES (PS_HALVES * 2 + K_ * 16 + NKG * GCW * 4)  // 61440+8192+8192=77824

__global__ __launch_bounds__(256) void gather_s(const float* __restrict__ b1,
                                                const int* __restrict__ raw) {
    extern __shared__ char gsm[];
    __half* Ps   = (__half*)gsm;                             // [3][160][64]
    int*   sidx4 = (int*)(gsm + PS_HALVES * 2);              // [512][4] interleaved
    float* part  = (float*)(gsm + PS_HALVES * 2 + K_ * 16);  // [32][64]

    int chunk = blockIdx.x;   // 0..15 (64-col chunks of the 1024-wide output)
    int t     = blockIdx.y;   // 0..15
    int tid = threadIdx.x;
    unsigned int is32 = g_oddor;

    // Stage P slice: slot s, row r, cols [s*1024 + chunk*64, +64)
    const __half* Pt = g_Ph + (size_t)t * SW * NP;
    for (int i = tid; i < PS_HALVES / 8; i += 256) {   // 3840 uint4
        int q = i & 7;                 // uint4 within row (8 per 64-half row)
        int r = (i >> 3) % SW;
        int s = i / (8 * SW);
        *(uint4*)(Ps + (s * SW + r) * GCW + q * 8) =
            *(const uint4*)(Pt + (size_t)r * NP + s * 1024 + chunk * GCW + q * 8);
    }

    int cs = (tid & 7) * 8;           // col-slot: 8 halves
    int kg = tid >> 3;                // k-group: 16 k each
    int col = chunk * GCW + cs;
    __half2 bbh[4];
#pragma unroll
    for (int j = 0; j < 4; j++) bbh[j] = __floats2half2_rn(b1[col + 2 * j], b1[col + 2 * j + 1]);
    const __half2 zero2 = __floats2half2_rn(0.f, 0.f);

    for (int w = 0; w < W_; w++) {
        __syncthreads();   // staging done (w=0) / part+sidx consumers done (w>0)
        int base = (t * W_ + w) * 3 * K_;
        for (int i = tid; i < 3 * K_; i += 256) {
            int v = is32 ? raw[base + i] : raw[2 * (base + i)];
            int slot = i >> 9, k = i & 511;
            sidx4[k * 4 + slot] = min(max(v, 0), SW - 1);
        }
        __syncthreads();

        __half2 acch[4] = {zero2, zero2, zero2, zero2};
#pragma unroll 4
        for (int k = kg * 16; k < kg * 16 + 16; k++) {
            int4 iv = *(int4*)&sidx4[k * 4];
            uint4 va = *(uint4*)(Ps + (size_t)iv.x * GCW + cs);
            uint4 vb = *(uint4*)(Ps + (SW + (size_t)iv.y) * GCW + cs);
            uint4 vc = *(uint4*)(Ps + (2 * SW + (size_t)iv.z) * GCW + cs);
            const __half2* ha = (const __half2*)&va;
            const __half2* hb = (const __half2*)&vb;
            const __half2* hc = (const __half2*)&vc;
#pragma unroll
            for (int j = 0; j < 4; j++) {
                __half2 z = __hadd2(__hadd2(ha[j], hb[j]), __hadd2(hc[j], bbh[j]));
                acch[j] = __hadd2(acch[j], __hmax2(z, zero2));
            }
        }
        // fp16 group sums -> fp32 partials, tree-reduce across the 32 k-groups
#pragma unroll
        for (int j = 0; j < 4; j++) {
            float2 f = __half22float2(acch[j]);
            *(float2*)&part[kg * GCW + cs + 2 * j] = f;
        }
        __syncthreads();
        if (tid < GCW) {
            float s = 0.f;
#pragma unroll
            for (int g = 0; g < NKG; g++) s += part[g * GCW + tid];
            g_r[(size_t)(t * W_ + w) * TWOD + chunk * GCW + tid] = s;
        }
    }
}

// ---------------------------------------------------------------------------
// Small-M k-split GEMM: Cm += A[k-slice] @ B[k-slice] (atomicAdd), bias from z==0.
// RELUA applies relu to A elements on load. BM=32, BN=64, BK=16, 256 threads.
template <bool RELUA>
__global__ __launch_bounds__(256) void gemm_ks(const float* __restrict__ A,
                                               const float* __restrict__ B,
                                               const float* __restrict__ bias,
                                               float bscale,
                                               float* __restrict__ Cm,
                                               int M, int N, int Kd) {
    __shared__ float As[16][33];
    __shared__ float Bs[16][64];
    int col0 = blockIdx.x * 64;
    int row0 = blockIdx.y * 32;
    int tid = threadIdx.x;
    int tx = tid & 15, ty = tid >> 4;
    int klen = Kd / gridDim.z;
    int kbeg = blockIdx.z * klen, kend = kbeg + klen;
    float acc[2][4] = {};

    for (int k0 = kbeg; k0 < kend; k0 += 16) {
#pragma unroll
        for (int l = 0; l < 2; l++) {
            int e = tid + l * 256;
            int m = e >> 4, kk = e & 15;
            float v = A[(size_t)(row0 + m) * Kd + k0 + kk];
            if (RELUA) v = fmaxf(v, 0.f);
            As[kk][m] = v;
        }
        {
            int kk = tid >> 4, c = (tid & 15) * 4;
            *(float4*)&Bs[kk][c] = *(const float4*)(B + (size_t)(k0 + kk) * N + col0 + c);
        }
        __syncthreads();
#pragma unroll
        for (int kk = 0; kk < 16; kk++) {
            float a0 = As[kk][ty * 2], a1 = As[kk][ty * 2 + 1];
            float4 b = *(const float4*)&Bs[kk][tx * 4];
            acc[0][0] = fmaf(a0, b.x, acc[0][0]);
            acc[0][1] = fmaf(a0, b.y, acc[0][1]);
            acc[0][2] = fmaf(a0, b.z, acc[0][2]);
            acc[0][3] = fmaf(a0, b.w, acc[0][3]);
            acc[1][0] = fmaf(a1, b.x, acc[1][0]);
            acc[1][1] = fmaf(a1, b.y, acc[1][1]);
            acc[1][2] = fmaf(a1, b.z, acc[1][2]);
            acc[1][3] = fmaf(a1, b.w, acc[1][3]);
        }
        __syncthreads();
    }
#pragma unroll
    for (int i = 0; i < 2; i++) {
        int row = row0 + ty * 2 + i;
#pragma unroll
        for (int j = 0; j < 4; j++) {
            int colx = col0 + tx * 4 + j;
            float v = acc[i][j];
            if (blockIdx.z == 0) v += bias[colx] * bscale;
            atomicAdd(&Cm[(size_t)row * N + colx], v);
        }
    }
}

// ---------------------------------------------------------------------------
// score = o @ Wc + bc, softmax over C_=64. 256 threads: 64 cols x 4 k-slices.
__global__ __launch_bounds__(256) void score_softmax(const float* __restrict__ Wc,
                                                     const float* __restrict__ bc,
                                                     float* __restrict__ out) {
    int row = blockIdx.x;
    int tid = threadIdx.x;
    __shared__ float so[D_];
    __shared__ float part[4][C_];
    __shared__ float red[2], red2[2];
    for (int e = tid; e < D_; e += 256) so[e] = g_o[(size_t)row * D_ + e];
    __syncthreads();

    int col = tid & 63, sl = tid >> 6;
    float acc = (sl == 0) ? bc[col] : 0.f;
#pragma unroll 4
    for (int k = sl * 128; k < sl * 128 + 128; k++)
        acc = fmaf(so[k], Wc[(size_t)k * C_ + col], acc);
    part[sl][col] = acc;
    __syncthreads();

    float sc = 0.f, e = 0.f;
    if (tid < C_) {
        sc = part[0][tid] + part[1][tid] + part[2][tid] + part[3][tid];
        float m = sc;
#pragma unroll
        for (int off = 16; off > 0; off >>= 1) m = fmaxf(m, __shfl_xor_sync(0xffffffffu, m, off));
        if ((tid & 31) == 0) red[tid >> 5] = m;
    }
    __syncthreads();
    if (tid < C_) {
        float m = fmaxf(red[0], red[1]);
        e = expf(sc - m);
        float s = e;
#pragma unroll
        for (int off = 16; off > 0; off >>= 1) s += __shfl_xor_sync(0xffffffffu, s, off);
        if ((tid & 31) == 0) red2[tid >> 5] = s;
    }
    __syncthreads();
    if (tid < C_) out[(size_t)row * C_ + tid] = e / (red2[0] + red2[1]);
}

// ---------------------------------------------------------------------------
extern "C" void kernel_launch(void* const* d_in, const int* in_sizes, int n_in,
                              void* d_out, int out_size) {
    const float* x    = (const float*)d_in[0];
    const void*  tidx = d_in[1];                 // int32 or int64 — probed on device
    const float* W1   = (const float*)d_in[2];
    const float* b1   = (const float*)d_in[3];
    const float* W2   = (const float*)d_in[4];
    const float* b2   = (const float*)d_in[5];
    const float* W3   = (const float*)d_in[6];
    const float* b3   = (const float*)d_in[7];
    const float* W4   = (const float*)d_in[8];
    const float* b4   = (const float*)d_in[9];
    const float* Wc   = (const float*)d_in[10];
    const float* bc   = (const float*)d_in[11];
    float* out = (float*)d_out;

    void *pr, *pg, *ph3, *po;
    cudaGetSymbolAddress(&pr, g_r);
    cudaGetSymbolAddress(&pg, g_g);
    cudaGetSymbolAddress(&ph3, g_h3);
    cudaGetSymbolAddress(&po, g_o);

    cudaFuncSetAttribute(gemm_fp16, cudaFuncAttributeMaxDynamicSharedMemorySize,
                         GEMM_SMEM);
    cudaFuncSetAttribute(gather_s, cudaFuncAttributeMaxDynamicSharedMemorySize,
                         GSM_BYTES);

    // 1) fp16 A + zero accumulators + inline dtype probe
    prep_a<<<(M_ * D_ / 4 + 255) / 256, 256>>>(x, (const unsigned int*)tidx);
    // 2) fp16 B^T (coalesced transpose)
    prep_b<<<dim3(TWOD / 32, D_ / 32, 3), 256>>>(W1);

    // 3) P(fp16) = A @ B^T  (fp16 GEMM, K=512, 4-stage cp.async, 2 CTAs/SM)
    gemm_fp16<<<dim3(NP / 128, M_ / 128), 256, GEMM_SMEM>>>();

    // 4) smem-staged gather+relu+k-sum -> r  (profiled slot; 256 blocks, R13 grid)
    gather_s<<<dim3(TWOD / GCW, T_), 256, GSM_BYTES>>>(b1, (const int*)tidx);

    // 5) g = r @ W2 + K_*b2        (160 x 512, K=1024, 16-way k-split)
    gemm_ks<false><<<dim3(D_ / 64, 5, 16), 256>>>(
        (const float*)pr, W2, b2, (float)K_, (float*)pg, T_ * W_, D_, TWOD);

    // 6) h3_pre = g @ W3 + b3      (160 x 1024, K=512, 8-way k-split; relu deferred)
    gemm_ks<false><<<dim3(TWOD / 64, 5, 8), 256>>>(
        (const float*)pg, W3, b3, 1.f, (float*)ph3, T_ * W_, TWOD, D_);

    // 7) o = relu(h3_pre) @ W4 + b4 (160 x 512, K=1024, 16-way k-split)
    gemm_ks<true><<<dim3(D_ / 64, 5, 16), 256>>>(
        (const float*)ph3, W4, b4, 1.f, (float*)po, T_ * W_, D_, TWOD);

    // 8) score + softmax -> out    (160 x 64)
    score_softmax<<<T_ * W_, 256>>>(Wc, bc, out);
}

// round 16
// speedup vs baseline: 1.6119x; 1.0506x over previous
#include <cuda_runtime.h>
#include <cuda_fp16.h>
#include <mma.h>
#include <cstdint>

using namespace nvcuda;

#define T_ 16
#define S_ 16
#define W_ 10
#define D_ 512
#define C_ 64
#define K_ 512
#define SW 160        // S_*W_
#define TWOD 1024
#define NP 3072       // 3 * TWOD
#define NIDX (T_ * W_ * 3 * K_)   // 245760 indices
#define M_ (T_ * SW)              // 2560 rows of P

// ---------------------------------------------------------------------------
// Device globals (no allocation allowed)
__device__ __half g_Ah[(size_t)M_ * D_];  // [2560][512] fp16 A
__device__ __half g_Bh[(size_t)NP * D_];  // [3072][512] fp16 B^T
__device__ __half g_Ph[(size_t)M_ * NP];  // P in fp16  [2560][3072]
__device__ float g_r[T_ * W_ * TWOD];     // 160 x 1024  sum_k relu(z)
__device__ float g_g[T_ * W_ * D_];       // 160 x 512
__device__ float g_h3[T_ * W_ * TWOD];    // 160 x 1024 (pre-relu)
__device__ float g_o[T_ * W_ * D_];       // 160 x 512
__device__ unsigned int g_oddor = 0u;     // dtype probe (never reset: atomicOr over
                                          // identical data is idempotent => deterministic)

// ---------------------------------------------------------------------------
__device__ __forceinline__ void cp_async16(void* dst, const void* src) {
    uint32_t d;
    asm("{ .reg .u64 t; cvta.to.shared.u64 t, %1; cvt.u32.u64 %0, t; }" : "=r"(d) : "l"(dst));
    asm volatile("cp.async.cg.shared.global [%0], [%1], 16;" :: "r"(d), "l"(src));
}

// ---------------------------------------------------------------------------
// X (2560x512 fp32) -> fp16 A; zeros g/h3/o; inline dtype probe (odd-word OR:
// int64 layout -> 0, int32 layout -> nonzero w.h.p.).
__global__ void prep_a(const float* __restrict__ x, const unsigned int* __restrict__ raw) {
    int i = blockIdx.x * 256 + threadIdx.x;     // i indexes groups of 4 elements
    unsigned int v = (i < NIDX / 2) ? raw[2 * i + 1] : 0u;
#pragma unroll
    for (int off = 16; off > 0; off >>= 1) v |= __shfl_xor_sync(0xffffffffu, v, off);
    if ((threadIdx.x & 31) == 0 && v) atomicOr(&g_oddor, v);

    if (i < T_ * W_ * TWOD) g_h3[i] = 0.f;
    if (i < T_ * W_ * D_) { g_g[i] = 0.f; g_o[i] = 0.f; }
    if (i >= M_ * D_ / 4) return;
    float4 vv = *(const float4*)(x + (size_t)i * 4);
    __half2 h0 = __floats2half2_rn(vv.x, vv.y);
    __half2 h1 = __floats2half2_rn(vv.z, vv.w);
    uint2 o = {*(uint32_t*)&h0, *(uint32_t*)&h1};
    *(uint2*)(g_Ah + (size_t)i * 4) = o;
}

// W1 (1536 x 1024) -> fp16 B^T [3072][512] via coalesced 32x32 smem transpose.
__global__ __launch_bounds__(256) void prep_b(const float* __restrict__ W1) {
    __shared__ float tile[32][33];
    int o0 = blockIdx.x * 32, k0 = blockIdx.y * 32, s = blockIdx.z;
    int tx = threadIdx.x & 31, ty = threadIdx.x >> 5;   // ty 0..7
#pragma unroll
    for (int i = 0; i < 4; i++) {
        int k = ty + i * 8;
        tile[k][tx] = W1[(size_t)(s * D_ + k0 + k) * TWOD + o0 + tx];
    }
    __syncthreads();
#pragma unroll
    for (int i = 0; i < 4; i++) {
        int o = ty + i * 8;
        g_Bh[(size_t)(s * TWOD + o0 + o) * D_ + k0 + tx] = __float2half_rn(tile[tx][o]);
    }
}

// ---------------------------------------------------------------------------
// fp16 GEMM, fp32 accum: P(fp16 2560x3072) = A (2560x512) @ B^T (3072x512)
// CTA 128x128, 8 warps (warp tile 32x64), BK=32, 4-stage cp.async ring, 2 CTAs/SM.
#define BK 32
#define KPAD 40
#define STG (128 * KPAD)             // halves per matrix per stage (5120)
#define NSTAGE 4
#define NCH (D_ / BK)                // 16 chunks
#define GEMM_SMEM (NSTAGE * 2 * STG * 2)   // 81920 bytes

__global__ __launch_bounds__(256, 2) void gemm_fp16() {
    extern __shared__ __half sh[];   // [4 stages][A 128x40 | B 128x40]

    int tid = threadIdx.x;
    int wid = tid >> 5, lane = tid & 31;
    int warp_m = wid & 3;    // 4 warps along M -> 32 rows each
    int warp_n = wid >> 2;   // 2 warps along N -> 64 cols each
    int row0 = blockIdx.y * 128;
    int col0 = blockIdx.x * 128;

    wmma::fragment<wmma::accumulator, 16, 16, 16, float> acc[2][4];
#pragma unroll
    for (int i = 0; i < 2; i++)
#pragma unroll
        for (int j = 0; j < 4; j++) wmma::fill_fragment(acc[i][j], 0.f);

    auto prefetch = [&](int c) {
        int s = c % NSTAGE;
        __half* As = sh + s * (2 * STG);
        __half* Bs = As + STG;
        int k0 = c * BK;
#pragma unroll
        for (int j = 0; j < 2; j++) {
            int idx = tid + j * 256;
            int r = idx >> 2, q = (idx & 3) * 8;
            cp_async16(&As[r * KPAD + q], g_Ah + (size_t)(row0 + r) * D_ + k0 + q);
            cp_async16(&Bs[r * KPAD + q], g_Bh + (size_t)(col0 + r) * D_ + k0 + q);
        }
        asm volatile("cp.async.commit_group;" ::: "memory");
    };

    prefetch(0);
    prefetch(1);
    prefetch(2);
    for (int c = 0; c < NCH; c++) {
        if (c < NCH - 2) {
            asm volatile("cp.async.wait_group 2;" ::: "memory");
        } else if (c == NCH - 2) {
            asm volatile("cp.async.wait_group 1;" ::: "memory");
        } else {
            asm volatile("cp.async.wait_group 0;" ::: "memory");
        }
        __syncthreads();
        if (c + 3 < NCH) prefetch(c + 3);

        const __half* As = sh + (c % NSTAGE) * (2 * STG);
        const __half* Bs = As + STG;
#pragma unroll
        for (int kk = 0; kk < BK; kk += 16) {
            wmma::fragment<wmma::matrix_a, 16, 16, 16, __half, wmma::row_major> fa[2];
            wmma::fragment<wmma::matrix_b, 16, 16, 16, __half, wmma::col_major> fb[4];
#pragma unroll
            for (int i = 0; i < 2; i++)
                wmma::load_matrix_sync(fa[i], As + (warp_m * 32 + i * 16) * KPAD + kk, KPAD);
#pragma unroll
            for (int j = 0; j < 4; j++)
                wmma::load_matrix_sync(fb[j], Bs + (warp_n * 64 + j * 16) * KPAD + kk, KPAD);
#pragma unroll
            for (int i = 0; i < 2; i++)
#pragma unroll
                for (int j = 0; j < 4; j++)
                    wmma::mma_sync(acc[i][j], fa[i], fb[j], acc[i][j]);
        }
    }
    __syncthreads();

    // Epilogue: per-warp 16x16 float patch in smem, convert to fp16, store P.
    float* patch = (float*)sh + wid * 256;
#pragma unroll
    for (int i = 0; i < 2; i++)
#pragma unroll
        for (int j = 0; j < 4; j++) {
            wmma::store_matrix_sync(patch, acc[i][j], 16, wmma::mem_row_major);
            __syncwarp();
            int m = row0 + warp_m * 32 + i * 16;
            int n = col0 + warp_n * 64 + j * 16;
            int pr = lane >> 1, pc = (lane & 1) * 8;
            __half2 o[4];
#pragma unroll
            for (int e = 0; e < 4; e++)
                o[e] = __floats2half2_rn(patch[pr * 16 + pc + 2 * e],
                                         patch[pr * 16 + pc + 2 * e + 1]);
            *(uint4*)(g_Ph + (size_t)(m + pr) * NP + n + pc) = *(uint4*)o;
            __syncwarp();
        }
}

// ---------------------------------------------------------------------------
// Smem-staged gather: 256 blocks (chunk, t), 512 threads = 8 col-slots x 64
// k-groups (8 k each). b1 folded into slot-2 rows at staging time. fp16 group
// accumulation; warp-shuffle reduce across the 4 k-groups per warp; fp32 final.
#define GCW 64
#define GTH 512
#define NWARP (GTH / 32)                       // 16 warps
#define PS_HALVES (3 * SW * GCW)               // 30720 halves (61440 B)
#define GSM_BYTES (PS_HALVES * 2 + K_ * 16 + NWARP * GCW * 4 + 128)
                                               // 61440 + 8192 + 4096 + 128 = 73856

__global__ __launch_bounds__(GTH) void gather_s(const float* __restrict__ b1,
                                                const int* __restrict__ raw) {
    extern __shared__ char gsm[];
    __half*  Ps    = (__half*)gsm;                            // [3][160][64]
    int*     sidx4 = (int*)(gsm + PS_HALVES * 2);             // [512][4] interleaved
    float*   part  = (float*)(gsm + PS_HALVES * 2 + K_ * 16); // [16][64]
    __half2* b1s   = (__half2*)(gsm + PS_HALVES * 2 + K_ * 16 + NWARP * GCW * 4); // [32]

    int chunk = blockIdx.x;   // 0..15 (64-col chunks of the 1024-wide output)
    int t     = blockIdx.y;   // 0..15
    int tid = threadIdx.x;
    int lane = tid & 31, wid = tid >> 5;
    unsigned int is32 = g_oddor;

    // b1 for this chunk -> smem (needed by slot-2 staging fold)
    if (tid < 32) b1s[tid] = __floats2half2_rn(b1[chunk * GCW + 2 * tid],
                                               b1[chunk * GCW + 2 * tid + 1]);
    __syncthreads();

    // Stage P slice: slot s, row r, cols [s*1024 + chunk*64, +64).
    // Slot 2 gets b1 added once here (reused 10*512 times below).
    const __half* Pt = g_Ph + (size_t)t * SW * NP;
    for (int i = tid; i < PS_HALVES / 8; i += GTH) {   // 3840 uint4
        int q = i & 7;                 // uint4 within row (8 per 64-half row)
        int r = (i >> 3) % SW;
        int s = i / (8 * SW);
        uint4 v = *(const uint4*)(Pt + (size_t)r * NP + s * 1024 + chunk * GCW + q * 8);
        if (s == 2) {
            __half2* hv = (__half2*)&v;
#pragma unroll
            for (int j = 0; j < 4; j++) hv[j] = __hadd2(hv[j], b1s[q * 4 + j]);
        }
        *(uint4*)(Ps + (s * SW + r) * GCW + q * 8) = v;
    }

    int cs = (tid & 7) * 8;           // col-slot: 8 halves
    int kg = tid >> 3;                // k-group: 8 k each (0..63)
    const __half2 zero2 = __floats2half2_rn(0.f, 0.f);

    for (int w = 0; w < W_; w++) {
        __syncthreads();   // staging done (w=0) / part+sidx consumers done (w>0)
        int base = (t * W_ + w) * 3 * K_;
        for (int i = tid; i < 3 * K_; i += GTH) {
            int v = is32 ? raw[base + i] : raw[2 * (base + i)];
            int slot = i >> 9, k = i & 511;
            sidx4[k * 4 + slot] = min(max(v, 0), SW - 1);
        }
        __syncthreads();

        __half2 acch[4] = {zero2, zero2, zero2, zero2};
#pragma unroll
        for (int k = kg * 8; k < kg * 8 + 8; k++) {
            int4 iv = *(int4*)&sidx4[k * 4];
            uint4 va = *(uint4*)(Ps + (size_t)iv.x * GCW + cs);
            uint4 vb = *(uint4*)(Ps + (SW + (size_t)iv.y) * GCW + cs);
            uint4 vc = *(uint4*)(Ps + (2 * SW + (size_t)iv.z) * GCW + cs);
            const __half2* ha = (const __half2*)&va;
            const __half2* hb = (const __half2*)&vb;
            const __half2* hc = (const __half2*)&vc;
#pragma unroll
            for (int j = 0; j < 4; j++) {
                __half2 z = __hadd2(__hadd2(ha[j], hb[j]), hc[j]);   // b1 pre-folded
                acch[j] = __hadd2(acch[j], __hmax2(z, zero2));
            }
        }
        // fp16 group sums -> fp32; shuffle-reduce the 4 k-groups in this warp
        float f[8];
#pragma unroll
        for (int j = 0; j < 4; j++) {
            float2 t2 = __half22float2(acch[j]);
            f[2 * j] = t2.x; f[2 * j + 1] = t2.y;
        }
#pragma unroll
        for (int j = 0; j < 8; j++) {
            f[j] += __shfl_down_sync(0xffffffffu, f[j], 16);
            f[j] += __shfl_down_sync(0xffffffffu, f[j], 8);
        }
        if (lane < 8) {
#pragma unroll
            for (int j = 0; j < 4; j++)
                *(float2*)&part[wid * GCW + cs + 2 * j] = make_float2(f[2 * j], f[2 * j + 1]);
        }
        __syncthreads();
        if (tid < GCW) {
            float s = 0.f;
#pragma unroll
            for (int g = 0; g < NWARP; g++) s += part[g * GCW + tid];
            g_r[(size_t)(t * W_ + w) * TWOD + chunk * GCW + tid] = s;
        }
    }
}

// ---------------------------------------------------------------------------
// Small-M k-split GEMM: Cm += A[k-slice] @ B[k-slice] (atomicAdd), bias from z==0.
// RELUA applies relu to A elements on load. BM=32, BN=64, BK=16, 256 threads.
template <bool RELUA>
__global__ __launch_bounds__(256) void gemm_ks(const float* __restrict__ A,
                                               const float* __restrict__ B,
                                               const float* __restrict__ bias,
                                               float bscale,
                                               float* __restrict__ Cm,
                                               int M, int N, int Kd) {
    __shared__ float As[16][33];
    __shared__ float Bs[16][64];
    int col0 = blockIdx.x * 64;
    int row0 = blockIdx.y * 32;
    int tid = threadIdx.x;
    int tx = tid & 15, ty = tid >> 4;
    int klen = Kd / gridDim.z;
    int kbeg = blockIdx.z * klen, kend = kbeg + klen;
    float acc[2][4] = {};

    for (int k0 = kbeg; k0 < kend; k0 += 16) {
#pragma unroll
        for (int l = 0; l < 2; l++) {
            int e = tid + l * 256;
            int m = e >> 4, kk = e & 15;
            float v = A[(size_t)(row0 + m) * Kd + k0 + kk];
            if (RELUA) v = fmaxf(v, 0.f);
            As[kk][m] = v;
        }
        {
            int kk = tid >> 4, c = (tid & 15) * 4;
            *(float4*)&Bs[kk][c] = *(const float4*)(B + (size_t)(k0 + kk) * N + col0 + c);
        }
        __syncthreads();
#pragma unroll
        for (int kk = 0; kk < 16; kk++) {
            float a0 = As[kk][ty * 2], a1 = As[kk][ty * 2 + 1];
            float4 b = *(const float4*)&Bs[kk][tx * 4];
            acc[0][0] = fmaf(a0, b.x, acc[0][0]);
            acc[0][1] = fmaf(a0, b.y, acc[0][1]);
            acc[0][2] = fmaf(a0, b.z, acc[0][2]);
            acc[0][3] = fmaf(a0, b.w, acc[0][3]);
            acc[1][0] = fmaf(a1, b.x, acc[1][0]);
            acc[1][1] = fmaf(a1, b.y, acc[1][1]);
            acc[1][2] = fmaf(a1, b.z, acc[1][2]);
            acc[1][3] = fmaf(a1, b.w, acc[1][3]);
        }
        __syncthreads();
    }
#pragma unroll
    for (int i = 0; i < 2; i++) {
        int row = row0 + ty * 2 + i;
#pragma unroll
        for (int j = 0; j < 4; j++) {
            int colx = col0 + tx * 4 + j;
            float v = acc[i][j];
            if (blockIdx.z == 0) v += bias[colx] * bscale;
            atomicAdd(&Cm[(size_t)row * N + colx], v);
        }
    }
}

// ---------------------------------------------------------------------------
// score = o @ Wc + bc, softmax over C_=64. 256 threads: 64 cols x 4 k-slices.
__global__ __launch_bounds__(256) void score_softmax(const float* __restrict__ Wc,
                                                     const float* __restrict__ bc,
                                                     float* __restrict__ out) {
    int row = blockIdx.x;
    int tid = threadIdx.x;
    __shared__ float so[D_];
    __shared__ float part[4][C_];
    __shared__ float red[2], red2[2];
    for (int e = tid; e < D_; e += 256) so[e] = g_o[(size_t)row * D_ + e];
    __syncthreads();

    int col = tid & 63, sl = tid >> 6;
    float acc = (sl == 0) ? bc[col] : 0.f;
#pragma unroll 4
    for (int k = sl * 128; k < sl * 128 + 128; k++)
        acc = fmaf(so[k], Wc[(size_t)k * C_ + col], acc);
    part[sl][col] = acc;
    __syncthreads();

    float sc = 0.f, e = 0.f;
    if (tid < C_) {
        sc = part[0][tid] + part[1][tid] + part[2][tid] + part[3][tid];
        float m = sc;
#pragma unroll
        for (int off = 16; off > 0; off >>= 1) m = fmaxf(m, __shfl_xor_sync(0xffffffffu, m, off));
        if ((tid & 31) == 0) red[tid >> 5] = m;
    }
    __syncthreads();
    if (tid < C_) {
        float m = fmaxf(red[0], red[1]);
        e = expf(sc - m);
        float s = e;
#pragma unroll
        for (int off = 16; off > 0; off >>= 1) s += __shfl_xor_sync(0xffffffffu, s, off);
        if ((tid & 31) == 0) red2[tid >> 5] = s;
    }
    __syncthreads();
    if (tid < C_) out[(size_t)row * C_ + tid] = e / (red2[0] + red2[1]);
}

// ---------------------------------------------------------------------------
extern "C" void kernel_launch(void* const* d_in, const int* in_sizes, int n_in,
                              void* d_out, int out_size) {
    const float* x    = (const float*)d_in[0];
    const void*  tidx = d_in[1];                 // int32 or int64 — probed on device
    const float* W1   = (const float*)d_in[2];
    const float* b1   = (const float*)d_in[3];
    const float* W2   = (const float*)d_in[4];
    const float* b2   = (const float*)d_in[5];
    const float* W3   = (const float*)d_in[6];
    const float* b3   = (const float*)d_in[7];
    const float* W4   = (const float*)d_in[8];
    const float* b4   = (const float*)d_in[9];
    const float* Wc   = (const float*)d_in[10];
    const float* bc   = (const float*)d_in[11];
    float* out = (float*)d_out;

    void *pr, *pg, *ph3, *po;
    cudaGetSymbolAddress(&pr, g_r);
    cudaGetSymbolAddress(&pg, g_g);
    cudaGetSymbolAddress(&ph3, g_h3);
    cudaGetSymbolAddress(&po, g_o);

    cudaFuncSetAttribute(gemm_fp16, cudaFuncAttributeMaxDynamicSharedMemorySize,
                         GEMM_SMEM);
    cudaFuncSetAttribute(gather_s, cudaFuncAttributeMaxDynamicSharedMemorySize,
                         GSM_BYTES);

    // 1) fp16 A + zero accumulators + inline dtype probe
    prep_a<<<(M_ * D_ / 4 + 255) / 256, 256>>>(x, (const unsigned int*)tidx);
    // 2) fp16 B^T (coalesced transpose)
    prep_b<<<dim3(TWOD / 32, D_ / 32, 3), 256>>>(W1);

    // 3) P(fp16) = A @ B^T  (fp16 GEMM, K=512, 4-stage cp.async, 2 CTAs/SM)
    gemm_fp16<<<dim3(NP / 128, M_ / 128), 256, GEMM_SMEM>>>();

    // 4) smem-staged gather+relu+k-sum -> r  (profiled slot; 256 blocks x 512 thr)
    gather_s<<<dim3(TWOD / GCW, T_), GTH, GSM_BYTES>>>(b1, (const int*)tidx);

    // 5) g = r @ W2 + K_*b2        (160 x 512, K=1024, 16-way k-split)
    gemm_ks<false><<<dim3(D_ / 64, 5, 16), 256>>>(
        (const float*)pr, W2, b2, (float)K_, (float*)pg, T_ * W_, D_, TWOD);

    // 6) h3_pre = g @ W3 + b3      (160 x 1024, K=512, 8-way k-split; relu deferred)
    gemm_ks<false><<<dim3(TWOD / 64, 5, 8), 256>>>(
        (const float*)pg, W3, b3, 1.f, (float*)ph3, T_ * W_, TWOD, D_);

    // 7) o = relu(h3_pre) @ W4 + b4 (160 x 512, K=1024, 16-way k-split)
    gemm_ks<true><<<dim3(D_ / 64, 5, 16), 256>>>(
        (const float*)ph3, W4, b4, 1.f, (float*)po, T_ * W_, D_, TWOD);

    // 8) score + softmax -> out    (160 x 64)
    score_softmax<<<T_ * W_, 256>>>(Wc, bc, out);
}